// round 12
// baseline (speedup 1.0000x reference)
#include <cuda_runtime.h>
#include <math.h>
#include <stdint.h>

#define BT 32
#define DIM 64
#define HW 4096
#define IMOFF 8388608
#define LNEPS 1e-5f

// ---------------- scratch ----------------
__device__ __align__(16) float g_xc[(size_t)BT * HW * 128];   // LN'd conv input (pixel-major, tf32-rounded)
__device__ __align__(16) float g_x1r[(size_t)BT * DIM * HW];
__device__ __align__(16) float g_x1i[(size_t)BT * DIM * HW];
__device__ float g_ar[BT * DIM], g_ai[BT * DIM], g_fr[BT * DIM], g_fi[BT * DIM], g_sq[BT];
// pre-converted tf32 weights
__device__ __align__(16) uint32_t g_encB[128 * 128];   // [k][j] packed complex encode
__device__ __align__(16) uint32_t g_decB[128 * 64];    // [k][d] packed real-part decode
__device__ __align__(16) uint32_t g_w1t[4 * 16384];
__device__ __align__(16) uint32_t g_w2t[4 * 16384];
__device__ __align__(16) uint32_t g_cwt[9 * 128 * 128];

__device__ __forceinline__ float gelu_tanh(float x) {
    float t = 0.7978845608028654f * (x + 0.044715f * x * x * x);
    return 0.5f * x * (1.0f + tanhf(t));
}
__device__ __forceinline__ uint32_t f2tf32(float f) {
    uint32_t u; asm("cvt.rna.tf32.f32 %0, %1;" : "=r"(u) : "f"(f)); return u;
}
__device__ __forceinline__ void mma_tf32(float4& c, uint32_t a0, uint32_t a1, uint32_t a2,
                                         uint32_t a3, uint32_t b0, uint32_t b1) {
    asm volatile("mma.sync.aligned.m16n8k8.row.col.f32.tf32.tf32.f32 "
                 "{%0,%1,%2,%3}, {%4,%5,%6,%7}, {%8,%9}, {%0,%1,%2,%3};"
                 : "+f"(c.x), "+f"(c.y), "+f"(c.z), "+f"(c.w)
                 : "r"(a0), "r"(a1), "r"(a2), "r"(a3), "r"(b0), "r"(b1));
}

// ---------------- K-1: weight pre-conversion (tf32, packed) ----------------
__global__ void k_wprep(const float* __restrict__ encr, const float* __restrict__ enci,
                        const float* __restrict__ decr, const float* __restrict__ deci,
                        const float* __restrict__ w1, const float* __restrict__ w2,
                        const float* __restrict__ cw) {
    int i = blockIdx.x * 256 + threadIdx.x;
    if (i < 16384) {
        int k = i >> 7, j = i & 127;
        float v;
        if (k < 64) v = (j < 64) ? encr[k * 64 + j] : enci[k * 64 + j - 64];
        else { int k2 = k - 64;
               v = (j < 64) ? -enci[k2 * 64 + j] : encr[k2 * 64 + j - 64]; }
        g_encB[i] = f2tf32(v);
    }
    if (i < 8192) {
        int k = i >> 6, d = i & 63;
        float v = (k < 64) ? decr[k * 64 + d] : -deci[(k - 64) * 64 + d];
        g_decB[i] = f2tf32(v);
    }
    if (i < 65536) {
        g_w1t[i] = f2tf32(w1[i]);
        g_w2t[i] = f2tf32(w2[i]);
    }
    if (i < 147456) g_cwt[i] = f2tf32(cw[i]);
}

// ---------------- K0: per-(b,t,d) decay & forcing ----------------
__global__ void k_setup(const float* __restrict__ dt, const float* __restrict__ lam_re,
                        const float* __restrict__ lam_im) {
    int i = blockIdx.x * blockDim.x + threadIdx.x;
    if (i >= BT * DIM) return;
    int bt = i >> 6, d = i & 63;
    float dtv = dt[bt];
    float x = lam_re[d];
    float sp = (x > 20.f) ? x : log1pf(expf(x));
    float lr = -sp, li = lam_im[d];
    float er = expf(lr * dtv);
    float ar = er * cosf(li * dtv), ai = er * sinf(li * dtv);
    float den = lr * lr + li * li;
    g_ar[i] = ar; g_ai[i] = ai;
    g_fr[i] = ((ar - 1.f) * lr + ai * li) / den;
    g_fi[i] = (ai * lr - (ar - 1.f) * li) / den;
    if (d == 0) g_sq[bt] = 0.01f * sqrtf(dtv);
}

// ---------------- K1: spatial complex LayerNorm -> g_xc (tf32-rounded) ----------------
__global__ void k_sln(const float* __restrict__ xr, const float* __restrict__ xi,
                      const float* __restrict__ w, const float* __restrict__ b) {
    __shared__ float sh[128][65];
    __shared__ float smu[64], srs[64];
    int t = threadIdx.x;
    int p0 = blockIdx.x * 64;
    int bt = p0 >> 12, hw0 = p0 & 4095;
    for (int r = 0; r < 32; r++) {
        int idx = t + 256 * r;
        int c = idx >> 6, p = idx & 63;
        float v = (c < 64) ? xr[((size_t)(bt * 64 + c)) * 4096 + hw0 + p]
                           : xi[((size_t)(bt * 64 + c - 64)) * 4096 + hw0 + p];
        sh[c][p] = v;
    }
    __syncthreads();
    int wid = t >> 5, lane = t & 31;
    if (wid < 8) {
        for (int pp = 0; pp < 8; pp++) {
            int p = wid * 8 + pp;
            float s = 0.f, s2 = 0.f;
            for (int cc = lane; cc < 128; cc += 32) {
                float v = sh[cc][p]; s += v; s2 += v * v;
            }
            for (int o = 16; o; o >>= 1) {
                s += __shfl_xor_sync(0xffffffffu, s, o);
                s2 += __shfl_xor_sync(0xffffffffu, s2, o);
            }
            if (lane == 0) {
                float mu = s * (1.f / 128.f);
                smu[p] = mu;
                srs[p] = rsqrtf(s2 * (1.f / 128.f) - mu * mu + LNEPS);
            }
        }
    }
    __syncthreads();
    for (int r = 0; r < 32; r++) {
        int idx = t + 256 * r;
        int p = idx >> 7, c = idx & 127;
        float v = (sh[c][p] - smu[p]) * srs[p] * w[c] + b[c];
        g_xc[((size_t)(p0 + p)) * 128 + c] = __uint_as_float(f2tf32(v));
    }
}

// ---------------- K2: 3x3 conv via tf32 mma, 256-px tile, 512 thr ----------------
// tile = 4 h-rows x 64 w x 128 co. 16 warps wm(4, h-row) x wn(4, 32-co group).
#define CONV_ASTR 36
#define CONV_BSTR 136
__global__ __launch_bounds__(512, 1) void k_conv(
        const float* __restrict__ cb,
        const float* __restrict__ xr, const float* __restrict__ xi) {
    extern __shared__ uint32_t cs[];
    uint32_t* A = cs;                          // [6*66][36] halo tile (1 kc chunk)
    uint32_t* B = cs + 396 * CONV_ASTR;        // [32][136]
    float* Cst = (float*)cs;                   // epilogue stage [128 co][130] (aliases A)
    int t = threadIdx.x;
    int h0 = blockIdx.x * 4, bt = blockIdx.y;
    int wrp = t >> 5, lane = t & 31;
    int wm = wrp & 3, wn = wrp >> 2;           // wm = h-row, wn = co group
    int qr = lane >> 2, qc = lane & 3;
    float4 acc[4][4];
#pragma unroll
    for (int i = 0; i < 4; i++)
#pragma unroll
        for (int j = 0; j < 4; j++) acc[i][j] = make_float4(0, 0, 0, 0);

    for (int kc = 0; kc < 4; kc++) {
        int ci0 = kc * 32;
        __syncthreads();
        // load halo A: 6 rows (h0-1 .. h0+4) x 66 x x 32 ci
        for (int r = 0; r < 6; r++) {
            int gh = h0 + r - 1;
            for (int idx = t; idx < 2112; idx += 512) {
                int xx = idx >> 5, c = idx & 31;
                int gw = xx - 1;
                float v = 0.f;
                if ((unsigned)gh < 64u && (unsigned)gw < 64u)
                    v = g_xc[((size_t)(bt * 4096 + gh * 64 + gw)) * 128 + ci0 + c];
                A[(r * 66 + xx) * CONV_ASTR + c] = __float_as_uint(v);
            }
        }
        for (int tap = 0; tap < 9; tap++) {
            int dy = tap / 3 - 1, dx = tap % 3 - 1;
            __syncthreads();
            for (int r = 0; r < 2; r++) {
                int idx = t + 512 * r;
                int kk = idx >> 5, j4 = idx & 31;
                *(uint4*)&B[kk * CONV_BSTR + j4 * 4] =
                    *(const uint4*)&g_cwt[(size_t)tap * 16384 + (ci0 + kk) * 128 + j4 * 4];
            }
            __syncthreads();
            // warp's A row base for this tap: row (wm+dy+1), x offset dx+1
            int rowoff = ((wm + dy + 1) * 66 + dx + 1) * CONV_ASTR;
#pragma unroll
            for (int ks = 0; ks < 4; ks++) {
                int acol = ks * 8 + qc;
                uint32_t af[4][4];
#pragma unroll
                for (int mt = 0; mt < 4; mt++) {
                    int xb = rowoff + (mt * 16 + qr) * CONV_ASTR + acol;
                    af[mt][0] = A[xb];
                    af[mt][1] = A[xb + 8 * CONV_ASTR];
                    af[mt][2] = A[xb + 4];
                    af[mt][3] = A[xb + 8 * CONV_ASTR + 4];
                }
                int br0 = (ks * 8 + qc) * CONV_BSTR;
                int br1 = br0 + 4 * CONV_BSTR;
#pragma unroll
                for (int nt = 0; nt < 4; nt++) {
                    int co = wn * 32 + nt * 8 + qr;
                    uint32_t b0 = B[br0 + co], b1 = B[br1 + co];
                    mma_tf32(acc[0][nt], af[0][0], af[0][1], af[0][2], af[0][3], b0, b1);
                    mma_tf32(acc[1][nt], af[1][0], af[1][1], af[1][2], af[1][3], b0, b1);
                    mma_tf32(acc[2][nt], af[2][0], af[2][1], af[2][2], af[2][3], b0, b1);
                    mma_tf32(acc[3][nt], af[3][0], af[3][1], af[3][2], af[3][3], b0, b1);
                }
            }
        }
    }
    // epilogue: two halves of 128 px through Cst [128 co][130]
    for (int half = 0; half < 2; half++) {
        __syncthreads();
        if ((wm >> 1) == half) {
            int mloc = (wm & 1) * 64;
#pragma unroll
            for (int mt = 0; mt < 4; mt++)
#pragma unroll
                for (int nt = 0; nt < 4; nt++) {
                    int m0 = mloc + mt * 16 + qr;
                    int n0 = wn * 32 + nt * 8 + 2 * qc;
                    float4 c = acc[mt][nt];
                    Cst[n0 * 130 + m0] = c.x;
                    Cst[(n0 + 1) * 130 + m0] = c.y;
                    Cst[n0 * 130 + m0 + 8] = c.z;
                    Cst[(n0 + 1) * 130 + m0 + 8] = c.w;
                }
        }
        __syncthreads();
        int p = t & 127, og = t >> 7;   // og 0..3
        int pxg = half * 128 + p;
        int y = pxg >> 6, x = pxg & 63;
        size_t pb = (size_t)(h0 + y) * 64 + x;
        for (int j = 0; j < 32; j++) {
            int co = og * 32 + j;
            float v = Cst[co * 130 + p] + cb[co];
            if (co < 64) {
                size_t gi = ((size_t)(bt * 64 + co)) * 4096 + pb;
                g_x1r[gi] = v + xr[gi];
            } else {
                size_t gi = ((size_t)(bt * 64 + co - 64)) * 4096 + pb;
                g_x1i[gi] = v + xi[gi];
            }
        }
    }
}

// ---------------- K3: temporal mega-kernel (unchanged from R11) ----------------
#define MT_ASTR 132
__global__ __launch_bounds__(512, 1) void k_temp(
        const float* __restrict__ ltw, const float* __restrict__ ltb,
        const float* __restrict__ sbr, const float* __restrict__ sbi,
        const float* __restrict__ nzr, const float* __restrict__ nzi,
        const float* __restrict__ rw, const float* __restrict__ rb,
        const float* __restrict__ b1, const float* __restrict__ b2,
        float* __restrict__ out) {
    extern __shared__ uint32_t ts[];
    float*    X1   = (float*)ts;
    uint32_t* WORK = ts + 16896;
    uint32_t* HS   = ts + 2 * 16896;
    uint32_t* B    = ts + 3 * 16896;
    float*    G    = (float*)(ts + 3 * 16896 + 4352);
    float*    smu  = G + 512;
    float*    srs  = smu + 128;
    float* WORKf = (float*)WORK;
    float* DRf   = (float*)HS;
    float* CstF  = (float*)WORK;
    int t = threadIdx.x;
    int hw0 = blockIdx.x * 8;
    int b = blockIdx.y;
    int wrp = t >> 5, lane = t & 31;
    int wm = wrp & 3, wn = wrp >> 2;
    int qr = lane >> 2, qc = lane & 3;

    for (int r = 0; r < 32; r++) {
        int idx = t + 512 * r;
        int hwi = idx & 7, c = (idx >> 3) & 127, tt = idx >> 10;
        int bt = b * 16 + tt;
        float v = (c < 64) ? g_x1r[((size_t)(bt * 64 + c)) * 4096 + hw0 + hwi]
                           : g_x1i[((size_t)(bt * 64 + c - 64)) * 4096 + hw0 + hwi];
        X1[(tt * 8 + hwi) * MT_ASTR + c] = v;
    }
    __syncthreads();
    for (int sub = 0; sub < 8; sub++) {
        int tok = wrp * 8 + sub;
        float s = 0.f, s2 = 0.f;
        for (int k = lane; k < 128; k += 32) {
            float v = X1[tok * MT_ASTR + k]; s += v; s2 += v * v;
        }
        for (int o = 16; o; o >>= 1) {
            s += __shfl_xor_sync(0xffffffffu, s, o);
            s2 += __shfl_xor_sync(0xffffffffu, s2, o);
        }
        if (lane == 0) {
            float mu = s * (1.f / 128.f);
            smu[tok] = mu;
            srs[tok] = rsqrtf(s2 * (1.f / 128.f) - mu * mu + LNEPS);
        }
    }
    __syncthreads();
    for (int r = 0; r < 32; r++) {
        int idx = t + 512 * r;
        int tok = idx >> 7, k = idx & 127;
        float v = (X1[tok * MT_ASTR + k] - smu[tok]) * srs[tok] * ltw[k] + ltb[k];
        WORK[tok * MT_ASTR + k] = f2tf32(v);
    }
    {
        float4 acc[2][4];
#pragma unroll
        for (int i = 0; i < 2; i++)
#pragma unroll
            for (int j = 0; j < 4; j++) acc[i][j] = make_float4(0, 0, 0, 0);
        for (int kc = 0; kc < 4; kc++) {
            __syncthreads();
            for (int r = 0; r < 2; r++) {
                int idx = t + 512 * r;
                int kk = idx >> 5, j4 = idx & 31;
                *(uint4*)&B[kk * 136 + j4 * 4] =
                    *(const uint4*)&g_encB[(kc * 32 + kk) * 128 + j4 * 4];
            }
            __syncthreads();
#pragma unroll
            for (int ks = 0; ks < 4; ks++) {
                int acol = kc * 32 + ks * 8 + qc;
                uint32_t af[2][4];
#pragma unroll
                for (int mt = 0; mt < 2; mt++) {
                    int base = (wm * 32 + mt * 16) * MT_ASTR;
                    af[mt][0] = WORK[base + qr * MT_ASTR + acol];
                    af[mt][1] = WORK[base + (qr + 8) * MT_ASTR + acol];
                    af[mt][2] = WORK[base + qr * MT_ASTR + acol + 4];
                    af[mt][3] = WORK[base + (qr + 8) * MT_ASTR + acol + 4];
                }
                int br0 = (ks * 8 + qc) * 136, br1 = br0 + 4 * 136;
#pragma unroll
                for (int nt = 0; nt < 4; nt++) {
                    int j = wn * 32 + nt * 8 + qr;
                    uint32_t b0 = B[br0 + j], b1v = B[br1 + j];
                    mma_tf32(acc[0][nt], af[0][0], af[0][1], af[0][2], af[0][3], b0, b1v);
                    mma_tf32(acc[1][nt], af[1][0], af[1][1], af[1][2], af[1][3], b0, b1v);
                }
            }
        }
        __syncthreads();
#pragma unroll
        for (int mt = 0; mt < 2; mt++)
#pragma unroll
            for (int nt = 0; nt < 4; nt++) {
                int tok0 = wm * 32 + mt * 16 + qr;
                int j0 = wn * 32 + nt * 8 + 2 * qc;
                float4 c = acc[mt][nt];
                CstF[j0 * 130 + tok0] = c.x;
                CstF[(j0 + 1) * 130 + tok0] = c.y;
                CstF[j0 * 130 + tok0 + 8] = c.z;
                CstF[(j0 + 1) * 130 + tok0 + 8] = c.w;
            }
    }
    __syncthreads();
    {
        float ureg[32];
        for (int r = 0; r < 16; r++) {
            int p = t + 512 * r;
            int e = p & 63, tok = p >> 6;
            int tt = tok >> 3, hwi = tok & 7;
            int bt = b * 16 + tt;
            int ai_ = bt * 64 + e;
            float ur = CstF[e * 130 + tok] + sbr[e];
            float ui = CstF[(e + 64) * 130 + tok] + sbi[e];
            float fr = g_fr[ai_], fi_ = g_fi[ai_], sq = g_sq[bt];
            size_t nb = ((size_t)(b * 4096 + hw0 + hwi) * 16 + tt) * 64 + e;
            ureg[2 * r]     = ur * fr - ui * fi_ + sq * nzr[nb];
            ureg[2 * r + 1] = ur * fi_ + ui * fr + sq * nzi[nb];
        }
        __syncthreads();
        for (int r = 0; r < 16; r++) {
            int p = t + 512 * r;
            int e = p & 63, tok = p >> 6;
            WORK[tok * MT_ASTR + e]      = __float_as_uint(ureg[2 * r]);
            WORK[tok * MT_ASTR + 64 + e] = __float_as_uint(ureg[2 * r + 1]);
        }
    }
    __syncthreads();
    {
        int e = t & 63, hwi = t >> 6;
        float hr = 0.f, hi = 0.f;
        for (int tt = 0; tt < 16; tt++) {
            int tok = tt * 8 + hwi;
            float ur = WORKf[tok * MT_ASTR + e];
            float ui = WORKf[tok * MT_ASTR + 64 + e];
            int ai_ = (b * 16 + tt) * 64 + e;
            float ar = g_ar[ai_], aiv = g_ai[ai_];
            float nhr = ar * hr - aiv * hi + ur;
            float nhi = ar * hi + aiv * hr + ui;
            hr = nhr; hi = nhi;
            WORK[tok * MT_ASTR + e]      = f2tf32(hr);
            WORK[tok * MT_ASTR + 64 + e] = f2tf32(hi);
        }
    }
    __syncthreads();
    {
        float4 dacc[2][2];
#pragma unroll
        for (int i = 0; i < 2; i++)
#pragma unroll
            for (int j = 0; j < 2; j++) dacc[i][j] = make_float4(0, 0, 0, 0);
        for (int kc = 0; kc < 4; kc++) {
            __syncthreads();
            {
                int kk = t >> 4, d4 = t & 15;
                *(uint4*)&B[kk * 72 + d4 * 4] =
                    *(const uint4*)&g_decB[(kc * 32 + kk) * 64 + d4 * 4];
            }
            __syncthreads();
#pragma unroll
            for (int ks = 0; ks < 4; ks++) {
                int acol = kc * 32 + ks * 8 + qc;
                uint32_t af[2][4];
#pragma unroll
                for (int mt = 0; mt < 2; mt++) {
                    int base = (wm * 32 + mt * 16) * MT_ASTR;
                    af[mt][0] = WORK[base + qr * MT_ASTR + acol];
                    af[mt][1] = WORK[base + (qr + 8) * MT_ASTR + acol];
                    af[mt][2] = WORK[base + qr * MT_ASTR + acol + 4];
                    af[mt][3] = WORK[base + (qr + 8) * MT_ASTR + acol + 4];
                }
                int br0 = (ks * 8 + qc) * 72, br1 = br0 + 4 * 72;
#pragma unroll
                for (int nt = 0; nt < 2; nt++) {
                    int j = wn * 16 + nt * 8 + qr;
                    uint32_t b0 = B[br0 + j], b1v = B[br1 + j];
                    mma_tf32(dacc[0][nt], af[0][0], af[0][1], af[0][2], af[0][3], b0, b1v);
                    mma_tf32(dacc[1][nt], af[1][0], af[1][1], af[1][2], af[1][3], b0, b1v);
                }
            }
        }
        __syncthreads();
#pragma unroll
        for (int mt = 0; mt < 2; mt++)
#pragma unroll
            for (int nt = 0; nt < 2; nt++) {
                int tok0 = wm * 32 + mt * 16 + qr;
                int d0 = wn * 16 + nt * 8 + 2 * qc;
                float4 c = dacc[mt][nt];
                DRf[d0 * 130 + tok0] = c.x;
                DRf[(d0 + 1) * 130 + tok0] = c.y;
                DRf[d0 * 130 + tok0 + 8] = c.z;
                DRf[(d0 + 1) * 130 + tok0 + 8] = c.w;
            }
    }
    __syncthreads();
    for (int r = 0; r < 32; r++) {
        int idx = t + 512 * r;
        int tok = idx >> 7, c = idx & 127;
        float v = X1[tok * MT_ASTR + c];
        if (c < 64) v += DRf[c * 130 + tok];
        X1[tok * MT_ASTR + c] = v;
        WORK[tok * MT_ASTR + c] = f2tf32(v);
    }
    __syncthreads();
    {
        int tok = t & 127, e = t >> 7;
        float l = rb[e];
        for (int c = 0; c < 128; c++)
            l = fmaf(WORKf[tok * MT_ASTR + c], rw[c * 4 + e], l);
        G[e * 128 + tok] = l;
    }
    __syncthreads();
    if (t < 128) {
        float l0 = G[t], l1 = G[128 + t], l2 = G[256 + t], l3 = G[384 + t];
        float m = fmaxf(fmaxf(l0, l1), fmaxf(l2, l3));
        float e0 = expf(l0 - m), e1 = expf(l1 - m), e2 = expf(l2 - m), e3 = expf(l3 - m);
        float inv = 1.f / (e0 + e1 + e2 + e3);
        G[t] = e0 * inv; G[128 + t] = e1 * inv;
        G[256 + t] = e2 * inv; G[384 + t] = e3 * inv;
    }
    float4 acc2[2][4];
#pragma unroll
    for (int i = 0; i < 2; i++)
#pragma unroll
        for (int j = 0; j < 4; j++) acc2[i][j] = make_float4(0, 0, 0, 0);

    for (int e = 0; e < 4; e++) {
        float4 acc1[2][4];
#pragma unroll
        for (int i = 0; i < 2; i++)
#pragma unroll
            for (int j = 0; j < 4; j++) acc1[i][j] = make_float4(0, 0, 0, 0);
        for (int kc = 0; kc < 4; kc++) {
            __syncthreads();
            for (int r = 0; r < 2; r++) {
                int idx = t + 512 * r;
                int kk = idx >> 5, j4 = idx & 31;
                *(uint4*)&B[kk * 136 + j4 * 4] =
                    *(const uint4*)&g_w1t[(size_t)e * 16384 + (kc * 32 + kk) * 128 + j4 * 4];
            }
            __syncthreads();
#pragma unroll
            for (int ks = 0; ks < 4; ks++) {
                int acol = kc * 32 + ks * 8 + qc;
                uint32_t af[2][4];
#pragma unroll
                for (int mt = 0; mt < 2; mt++) {
                    int base = (wm * 32 + mt * 16) * MT_ASTR;
                    af[mt][0] = WORK[base + qr * MT_ASTR + acol];
                    af[mt][1] = WORK[base + (qr + 8) * MT_ASTR + acol];
                    af[mt][2] = WORK[base + qr * MT_ASTR + acol + 4];
                    af[mt][3] = WORK[base + (qr + 8) * MT_ASTR + acol + 4];
                }
                int br0 = (ks * 8 + qc) * 136, br1 = br0 + 4 * 136;
#pragma unroll
                for (int nt = 0; nt < 4; nt++) {
                    int j = wn * 32 + nt * 8 + qr;
                    uint32_t b0 = B[br0 + j], b1v = B[br1 + j];
                    mma_tf32(acc1[0][nt], af[0][0], af[0][1], af[0][2], af[0][3], b0, b1v);
                    mma_tf32(acc1[1][nt], af[1][0], af[1][1], af[1][2], af[1][3], b0, b1v);
                }
            }
        }
#pragma unroll
        for (int mt = 0; mt < 2; mt++)
#pragma unroll
            for (int nt = 0; nt < 4; nt++) {
                int tok0 = wm * 32 + mt * 16 + qr;
                int j0 = wn * 32 + nt * 8 + 2 * qc;
                float4 c = acc1[mt][nt];
                float b1v0 = b1[e * 128 + j0], b1v1 = b1[e * 128 + j0 + 1];
                float g0 = G[e * 128 + tok0], g8 = G[e * 128 + tok0 + 8];
                HS[tok0 * MT_ASTR + j0]           = f2tf32(gelu_tanh(c.x + b1v0) * g0);
                HS[tok0 * MT_ASTR + j0 + 1]       = f2tf32(gelu_tanh(c.y + b1v1) * g0);
                HS[(tok0 + 8) * MT_ASTR + j0]     = f2tf32(gelu_tanh(c.z + b1v0) * g8);
                HS[(tok0 + 8) * MT_ASTR + j0 + 1] = f2tf32(gelu_tanh(c.w + b1v1) * g8);
            }
        for (int kc = 0; kc < 4; kc++) {
            __syncthreads();
            for (int r = 0; r < 2; r++) {
                int idx = t + 512 * r;
                int kk = idx >> 5, j4 = idx & 31;
                *(uint4*)&B[kk * 136 + j4 * 4] =
                    *(const uint4*)&g_w2t[(size_t)e * 16384 + (kc * 32 + kk) * 128 + j4 * 4];
            }
            __syncthreads();
#pragma unroll
            for (int ks = 0; ks < 4; ks++) {
                int acol = kc * 32 + ks * 8 + qc;
                uint32_t af[2][4];
#pragma unroll
                for (int mt = 0; mt < 2; mt++) {
                    int base = (wm * 32 + mt * 16) * MT_ASTR;
                    af[mt][0] = HS[base + qr * MT_ASTR + acol];
                    af[mt][1] = HS[base + (qr + 8) * MT_ASTR + acol];
                    af[mt][2] = HS[base + qr * MT_ASTR + acol + 4];
                    af[mt][3] = HS[base + (qr + 8) * MT_ASTR + acol + 4];
                }
                int br0 = (ks * 8 + qc) * 136, br1 = br0 + 4 * 136;
#pragma unroll
                for (int nt = 0; nt < 4; nt++) {
                    int j = wn * 32 + nt * 8 + qr;
                    uint32_t b0 = B[br0 + j], b1v = B[br1 + j];
                    mma_tf32(acc2[0][nt], af[0][0], af[0][1], af[0][2], af[0][3], b0, b1v);
                    mma_tf32(acc2[1][nt], af[1][0], af[1][1], af[1][2], af[1][3], b0, b1v);
                }
            }
        }
        __syncthreads();
    }
#pragma unroll
    for (int mt = 0; mt < 2; mt++)
#pragma unroll
        for (int nt = 0; nt < 4; nt++) {
            int tok0 = wm * 32 + mt * 16 + qr;
            int o0 = wn * 32 + nt * 8 + 2 * qc;
            float4 c = acc2[mt][nt];
            CstF[o0 * 130 + tok0] = c.x;
            CstF[(o0 + 1) * 130 + tok0] = c.y;
            CstF[o0 * 130 + tok0 + 8] = c.z;
            CstF[(o0 + 1) * 130 + tok0 + 8] = c.w;
        }
    __syncthreads();
    {
        int tl = t & 127, og = t >> 7;
        float g0 = G[tl], g1 = G[128 + tl], g2 = G[256 + tl], g3 = G[384 + tl];
        int tt = tl >> 3, hwi = tl & 7;
        int bt = b * 16 + tt;
        for (int j = 0; j < 32; j++) {
            int o = og * 32 + j;
            float delta = CstF[o * 130 + tl] +
                          g0 * b2[o] + g1 * b2[128 + o] + g2 * b2[256 + o] + g3 * b2[384 + o];
            float base = X1[tl * MT_ASTR + o];
            size_t gi = (o < 64)
                ? ((size_t)(bt * 64 + o)) * 4096 + hw0 + hwi
                : IMOFF + ((size_t)(bt * 64 + o - 64)) * 4096 + hw0 + hwi;
            out[gi] = base + delta;
        }
    }
}

extern "C" void kernel_launch(void* const* d_in, const int* in_sizes, int n_in,
                              void* d_out, int out_size) {
    const float* x_real = (const float*)d_in[0];
    const float* x_imag = (const float*)d_in[1];
    const float* dt     = (const float*)d_in[2];
    const float* nz_r   = (const float*)d_in[3];
    const float* nz_i   = (const float*)d_in[4];
    const float* ln_s_w = (const float*)d_in[5];
    const float* ln_s_b = (const float*)d_in[6];
    const float* conv_w = (const float*)d_in[7];
    const float* conv_b = (const float*)d_in[8];
    const float* ln_t_w = (const float*)d_in[9];
    const float* ln_t_b = (const float*)d_in[10];
    const float* lam_re = (const float*)d_in[11];
    const float* lam_im = (const float*)d_in[12];
    const float* sb_re  = (const float*)d_in[13];
    const float* sb_im  = (const float*)d_in[14];
    const float* enc_re = (const float*)d_in[15];
    const float* enc_im = (const float*)d_in[16];
    const float* dec_re = (const float*)d_in[17];
    const float* dec_im = (const float*)d_in[18];
    const float* rw     = (const float*)d_in[19];
    const float* rb     = (const float*)d_in[20];
    const float* w1     = (const float*)d_in[21];
    const float* b1     = (const float*)d_in[22];
    const float* w2     = (const float*)d_in[23];
    const float* b2     = (const float*)d_in[24];
    float* out = (float*)d_out;

    int conv_smem = (396 * CONV_ASTR + 32 * CONV_BSTR) * 4;     // 74432 B (Cst 66560 aliases)
    int temp_smem = (3 * 16896 + 4352 + 512 + 256) * 4;         // 223232 B
    cudaFuncSetAttribute(k_conv, cudaFuncAttributeMaxDynamicSharedMemorySize, conv_smem);
    cudaFuncSetAttribute(k_temp, cudaFuncAttributeMaxDynamicSharedMemorySize, temp_smem);

    k_wprep<<<576, 256>>>(enc_re, enc_im, dec_re, dec_im, w1, w2, conv_w);
    k_setup<<<8, 256>>>(dt, lam_re, lam_im);
    k_sln<<<2048, 256>>>(x_real, x_imag, ln_s_w, ln_s_b);
    k_conv<<<dim3(16, 32), 512, conv_smem>>>(conv_b, x_real, x_imag);
    k_temp<<<dim3(512, 2), 512, temp_smem>>>(ln_t_w, ln_t_b, sb_re, sb_im,
                                             nz_r, nz_i, rw, rb, b1, b2, out);
}

// round 13
// speedup vs baseline: 1.1606x; 1.1606x over previous
#include <cuda_runtime.h>
#include <math.h>
#include <stdint.h>

#define BT 32
#define DIM 64
#define HW 4096
#define IMOFF 8388608
#define LNEPS 1e-5f

// ---------------- scratch ----------------
__device__ __align__(16) float g_xc[(size_t)BT * HW * 128];   // LN'd conv input (pixel-major, tf32-rounded)
__device__ __align__(16) float g_x1r[(size_t)BT * DIM * HW];
__device__ __align__(16) float g_x1i[(size_t)BT * DIM * HW];
__device__ float g_ar[BT * DIM], g_ai[BT * DIM], g_fr[BT * DIM], g_fi[BT * DIM], g_sq[BT];
// pre-converted tf32 weights
__device__ __align__(16) uint32_t g_encB[128 * 128];   // [k][j] packed complex encode
__device__ __align__(16) uint32_t g_decB[128 * 64];    // [k][d] packed real-part decode
__device__ __align__(16) uint32_t g_w1t[4 * 16384];
__device__ __align__(16) uint32_t g_w2t[4 * 16384];
__device__ __align__(16) uint32_t g_cwt[9 * 128 * 128];

__device__ __forceinline__ float gelu_tanh(float x) {
    float t = 0.7978845608028654f * (x + 0.044715f * x * x * x);
    return 0.5f * x * (1.0f + tanhf(t));
}
__device__ __forceinline__ uint32_t f2tf32(float f) {
    uint32_t u; asm("cvt.rna.tf32.f32 %0, %1;" : "=r"(u) : "f"(f)); return u;
}
__device__ __forceinline__ void mma_tf32(float4& c, uint32_t a0, uint32_t a1, uint32_t a2,
                                         uint32_t a3, uint32_t b0, uint32_t b1) {
    asm volatile("mma.sync.aligned.m16n8k8.row.col.f32.tf32.tf32.f32 "
                 "{%0,%1,%2,%3}, {%4,%5,%6,%7}, {%8,%9}, {%0,%1,%2,%3};"
                 : "+f"(c.x), "+f"(c.y), "+f"(c.z), "+f"(c.w)
                 : "r"(a0), "r"(a1), "r"(a2), "r"(a3), "r"(b0), "r"(b1));
}

// ---------------- K-1: weight pre-conversion (tf32, packed) ----------------
__global__ void k_wprep(const float* __restrict__ encr, const float* __restrict__ enci,
                        const float* __restrict__ decr, const float* __restrict__ deci,
                        const float* __restrict__ w1, const float* __restrict__ w2,
                        const float* __restrict__ cw) {
    int i = blockIdx.x * 256 + threadIdx.x;
    if (i < 16384) {
        int k = i >> 7, j = i & 127;
        float v;
        if (k < 64) v = (j < 64) ? encr[k * 64 + j] : enci[k * 64 + j - 64];
        else { int k2 = k - 64;
               v = (j < 64) ? -enci[k2 * 64 + j] : encr[k2 * 64 + j - 64]; }
        g_encB[i] = f2tf32(v);
    }
    if (i < 8192) {
        int k = i >> 6, d = i & 63;
        float v = (k < 64) ? decr[k * 64 + d] : -deci[(k - 64) * 64 + d];
        g_decB[i] = f2tf32(v);
    }
    if (i < 65536) {
        g_w1t[i] = f2tf32(w1[i]);
        g_w2t[i] = f2tf32(w2[i]);
    }
    if (i < 147456) g_cwt[i] = f2tf32(cw[i]);
}

// ---------------- K0: per-(b,t,d) decay & forcing ----------------
__global__ void k_setup(const float* __restrict__ dt, const float* __restrict__ lam_re,
                        const float* __restrict__ lam_im) {
    int i = blockIdx.x * blockDim.x + threadIdx.x;
    if (i >= BT * DIM) return;
    int bt = i >> 6, d = i & 63;
    float dtv = dt[bt];
    float x = lam_re[d];
    float sp = (x > 20.f) ? x : log1pf(expf(x));
    float lr = -sp, li = lam_im[d];
    float er = expf(lr * dtv);
    float ar = er * cosf(li * dtv), ai = er * sinf(li * dtv);
    float den = lr * lr + li * li;
    g_ar[i] = ar; g_ai[i] = ai;
    g_fr[i] = ((ar - 1.f) * lr + ai * li) / den;
    g_fi[i] = (ai * lr - (ar - 1.f) * li) / den;
    if (d == 0) g_sq[bt] = 0.01f * sqrtf(dtv);
}

// ---------------- K1: spatial complex LayerNorm -> g_xc (tf32-rounded) ----------------
__global__ void k_sln(const float* __restrict__ xr, const float* __restrict__ xi,
                      const float* __restrict__ w, const float* __restrict__ b) {
    __shared__ float sh[128][65];
    __shared__ float smu[64], srs[64];
    int t = threadIdx.x;
    int p0 = blockIdx.x * 64;
    int bt = p0 >> 12, hw0 = p0 & 4095;
    for (int r = 0; r < 32; r++) {
        int idx = t + 256 * r;
        int c = idx >> 6, p = idx & 63;
        float v = (c < 64) ? xr[((size_t)(bt * 64 + c)) * 4096 + hw0 + p]
                           : xi[((size_t)(bt * 64 + c - 64)) * 4096 + hw0 + p];
        sh[c][p] = v;
    }
    __syncthreads();
    int wid = t >> 5, lane = t & 31;
    if (wid < 8) {
        for (int pp = 0; pp < 8; pp++) {
            int p = wid * 8 + pp;
            float s = 0.f, s2 = 0.f;
            for (int cc = lane; cc < 128; cc += 32) {
                float v = sh[cc][p]; s += v; s2 += v * v;
            }
            for (int o = 16; o; o >>= 1) {
                s += __shfl_xor_sync(0xffffffffu, s, o);
                s2 += __shfl_xor_sync(0xffffffffu, s2, o);
            }
            if (lane == 0) {
                float mu = s * (1.f / 128.f);
                smu[p] = mu;
                srs[p] = rsqrtf(s2 * (1.f / 128.f) - mu * mu + LNEPS);
            }
        }
    }
    __syncthreads();
    for (int r = 0; r < 32; r++) {
        int idx = t + 256 * r;
        int p = idx >> 7, c = idx & 127;
        float v = (sh[c][p] - smu[p]) * srs[p] * w[c] + b[c];
        g_xc[((size_t)(p0 + p)) * 128 + c] = __uint_as_float(f2tf32(v));
    }
}

// ---------------- K2: 3x3 conv via tf32 mma (256 thr, 128-px tile, 3-tap B staging) ----------------
#define CONV_ASTR 36
#define CONV_BSTR 136
__global__ void k_conv(const float* __restrict__ cb,
                       const float* __restrict__ xr, const float* __restrict__ xi) {
    extern __shared__ uint32_t cs[];
    uint32_t* A = cs;                       // [264][36] halo (4 rows x 66 x, 32 ci)
    uint32_t* B = cs + 264 * CONV_ASTR;     // [3 taps][32][136]
    float* Cst = (float*)cs;                // epilogue stage [128 co][130] (aliases A+B)
    int t = threadIdx.x;
    int h0 = blockIdx.x * 2, bt = blockIdx.y;
    int wrp = t >> 5, lane = t & 31;
    int wm = wrp & 3, wn = wrp >> 2;
    int qr = lane >> 2, qc = lane & 3;
    float4 acc[2][8];
#pragma unroll
    for (int i = 0; i < 2; i++)
#pragma unroll
        for (int j = 0; j < 8; j++) acc[i][j] = make_float4(0, 0, 0, 0);

    for (int kc = 0; kc < 4; kc++) {
        int ci0 = kc * 32;
        __syncthreads();
        // load halo A: rows h0-1 .. h0+2, x = -1..64
        for (int r = 0; r < 4; r++) {
            int gh = h0 + r - 1;
            for (int idx = t; idx < 2112; idx += 256) {
                int xx = idx >> 5, c = idx & 31;
                int gw = xx - 1;
                float v = 0.f;
                if ((unsigned)gh < 64u && (unsigned)gw < 64u)
                    v = g_xc[((size_t)(bt * 4096 + gh * 64 + gw)) * 128 + ci0 + c];
                A[(r * 66 + xx) * CONV_ASTR + c] = __float_as_uint(v);
            }
        }
        for (int dyg = 0; dyg < 3; dyg++) {
            int dy = dyg - 1;
            __syncthreads();
            // stage 3 taps (dx = -1,0,1) of B for this dy row
            for (int idx = t; idx < 3072; idx += 256) {
                int tap3 = idx >> 10;           // 0..2
                int rem = idx & 1023;           // 32k x 32 j4
                int kk = rem >> 5, j4 = rem & 31;
                *(uint4*)&B[tap3 * 4352 + kk * CONV_BSTR + j4 * 4] =
                    *(const uint4*)&g_cwt[(size_t)(dyg * 3 + tap3) * 16384 +
                                          (ci0 + kk) * 128 + j4 * 4];
            }
            __syncthreads();
#pragma unroll
            for (int dx3 = 0; dx3 < 3; dx3++) {
                int dx = dx3 - 1;
                int prs[4];
#pragma unroll
                for (int i = 0; i < 4; i++) {
                    int m = wm * 32 + i * 8 + qr;
                    int y = m >> 6, x = m & 63;
                    prs[i] = (y + dy + 1) * 66 + (x + dx + 1);
                }
#pragma unroll
                for (int ks = 0; ks < 4; ks++) {
                    int acol = ks * 8 + qc;
                    uint32_t af[4][2];
#pragma unroll
                    for (int i = 0; i < 4; i++) {
                        af[i][0] = A[prs[i] * CONV_ASTR + acol];
                        af[i][1] = A[prs[i] * CONV_ASTR + acol + 4];
                    }
                    int brow0 = dx3 * 4352 + (ks * 8 + qc) * CONV_BSTR;
                    int brow1 = brow0 + 4 * CONV_BSTR;
#pragma unroll
                    for (int nt = 0; nt < 8; nt++) {
                        int co = wn * 64 + nt * 8 + qr;
                        uint32_t b0 = B[brow0 + co], b1 = B[brow1 + co];
                        mma_tf32(acc[0][nt], af[0][0], af[1][0], af[0][1], af[1][1], b0, b1);
                        mma_tf32(acc[1][nt], af[2][0], af[3][0], af[2][1], af[3][1], b0, b1);
                    }
                }
            }
        }
    }
    __syncthreads();
#pragma unroll
    for (int mt = 0; mt < 2; mt++)
#pragma unroll
        for (int nt = 0; nt < 8; nt++) {
            int m0 = wm * 32 + mt * 16 + qr;
            int n0 = wn * 64 + nt * 8 + 2 * qc;
            float4 c = acc[mt][nt];
            Cst[n0 * 130 + m0] = c.x;
            Cst[(n0 + 1) * 130 + m0] = c.y;
            Cst[n0 * 130 + m0 + 8] = c.z;
            Cst[(n0 + 1) * 130 + m0 + 8] = c.w;
        }
    __syncthreads();
    int p = t & 127, og = t >> 7;
    size_t pb = (size_t)h0 * 64 + p;
    for (int j = 0; j < 64; j++) {
        int co = og * 64 + j;
        float v = Cst[co * 130 + p] + cb[co];
        if (co < 64) {
            size_t gi = ((size_t)(bt * 64 + co)) * 4096 + pb;
            g_x1r[gi] = v + xr[gi];
        } else {
            size_t gi = ((size_t)(bt * 64 + co - 64)) * 4096 + pb;
            g_x1i[gi] = v + xi[gi];
        }
    }
}

// ---------------- K3: temporal mega-kernel (unchanged from R11) ----------------
#define MT_ASTR 132
__global__ __launch_bounds__(512, 1) void k_temp(
        const float* __restrict__ ltw, const float* __restrict__ ltb,
        const float* __restrict__ sbr, const float* __restrict__ sbi,
        const float* __restrict__ nzr, const float* __restrict__ nzi,
        const float* __restrict__ rw, const float* __restrict__ rb,
        const float* __restrict__ b1, const float* __restrict__ b2,
        float* __restrict__ out) {
    extern __shared__ uint32_t ts[];
    float*    X1   = (float*)ts;
    uint32_t* WORK = ts + 16896;
    uint32_t* HS   = ts + 2 * 16896;
    uint32_t* B    = ts + 3 * 16896;
    float*    G    = (float*)(ts + 3 * 16896 + 4352);
    float*    smu  = G + 512;
    float*    srs  = smu + 128;
    float* WORKf = (float*)WORK;
    float* DRf   = (float*)HS;
    float* CstF  = (float*)WORK;
    int t = threadIdx.x;
    int hw0 = blockIdx.x * 8;
    int b = blockIdx.y;
    int wrp = t >> 5, lane = t & 31;
    int wm = wrp & 3, wn = wrp >> 2;
    int qr = lane >> 2, qc = lane & 3;

    for (int r = 0; r < 32; r++) {
        int idx = t + 512 * r;
        int hwi = idx & 7, c = (idx >> 3) & 127, tt = idx >> 10;
        int bt = b * 16 + tt;
        float v = (c < 64) ? g_x1r[((size_t)(bt * 64 + c)) * 4096 + hw0 + hwi]
                           : g_x1i[((size_t)(bt * 64 + c - 64)) * 4096 + hw0 + hwi];
        X1[(tt * 8 + hwi) * MT_ASTR + c] = v;
    }
    __syncthreads();
    for (int sub = 0; sub < 8; sub++) {
        int tok = wrp * 8 + sub;
        float s = 0.f, s2 = 0.f;
        for (int k = lane; k < 128; k += 32) {
            float v = X1[tok * MT_ASTR + k]; s += v; s2 += v * v;
        }
        for (int o = 16; o; o >>= 1) {
            s += __shfl_xor_sync(0xffffffffu, s, o);
            s2 += __shfl_xor_sync(0xffffffffu, s2, o);
        }
        if (lane == 0) {
            float mu = s * (1.f / 128.f);
            smu[tok] = mu;
            srs[tok] = rsqrtf(s2 * (1.f / 128.f) - mu * mu + LNEPS);
        }
    }
    __syncthreads();
    for (int r = 0; r < 32; r++) {
        int idx = t + 512 * r;
        int tok = idx >> 7, k = idx & 127;
        float v = (X1[tok * MT_ASTR + k] - smu[tok]) * srs[tok] * ltw[k] + ltb[k];
        WORK[tok * MT_ASTR + k] = f2tf32(v);
    }
    {
        float4 acc[2][4];
#pragma unroll
        for (int i = 0; i < 2; i++)
#pragma unroll
            for (int j = 0; j < 4; j++) acc[i][j] = make_float4(0, 0, 0, 0);
        for (int kc = 0; kc < 4; kc++) {
            __syncthreads();
            for (int r = 0; r < 2; r++) {
                int idx = t + 512 * r;
                int kk = idx >> 5, j4 = idx & 31;
                *(uint4*)&B[kk * 136 + j4 * 4] =
                    *(const uint4*)&g_encB[(kc * 32 + kk) * 128 + j4 * 4];
            }
            __syncthreads();
#pragma unroll
            for (int ks = 0; ks < 4; ks++) {
                int acol = kc * 32 + ks * 8 + qc;
                uint32_t af[2][4];
#pragma unroll
                for (int mt = 0; mt < 2; mt++) {
                    int base = (wm * 32 + mt * 16) * MT_ASTR;
                    af[mt][0] = WORK[base + qr * MT_ASTR + acol];
                    af[mt][1] = WORK[base + (qr + 8) * MT_ASTR + acol];
                    af[mt][2] = WORK[base + qr * MT_ASTR + acol + 4];
                    af[mt][3] = WORK[base + (qr + 8) * MT_ASTR + acol + 4];
                }
                int br0 = (ks * 8 + qc) * 136, br1 = br0 + 4 * 136;
#pragma unroll
                for (int nt = 0; nt < 4; nt++) {
                    int j = wn * 32 + nt * 8 + qr;
                    uint32_t b0 = B[br0 + j], b1v = B[br1 + j];
                    mma_tf32(acc[0][nt], af[0][0], af[0][1], af[0][2], af[0][3], b0, b1v);
                    mma_tf32(acc[1][nt], af[1][0], af[1][1], af[1][2], af[1][3], b0, b1v);
                }
            }
        }
        __syncthreads();
#pragma unroll
        for (int mt = 0; mt < 2; mt++)
#pragma unroll
            for (int nt = 0; nt < 4; nt++) {
                int tok0 = wm * 32 + mt * 16 + qr;
                int j0 = wn * 32 + nt * 8 + 2 * qc;
                float4 c = acc[mt][nt];
                CstF[j0 * 130 + tok0] = c.x;
                CstF[(j0 + 1) * 130 + tok0] = c.y;
                CstF[j0 * 130 + tok0 + 8] = c.z;
                CstF[(j0 + 1) * 130 + tok0 + 8] = c.w;
            }
    }
    __syncthreads();
    {
        float ureg[32];
        for (int r = 0; r < 16; r++) {
            int p = t + 512 * r;
            int e = p & 63, tok = p >> 6;
            int tt = tok >> 3, hwi = tok & 7;
            int bt = b * 16 + tt;
            int ai_ = bt * 64 + e;
            float ur = CstF[e * 130 + tok] + sbr[e];
            float ui = CstF[(e + 64) * 130 + tok] + sbi[e];
            float fr = g_fr[ai_], fi_ = g_fi[ai_], sq = g_sq[bt];
            size_t nb = ((size_t)(b * 4096 + hw0 + hwi) * 16 + tt) * 64 + e;
            ureg[2 * r]     = ur * fr - ui * fi_ + sq * nzr[nb];
            ureg[2 * r + 1] = ur * fi_ + ui * fr + sq * nzi[nb];
        }
        __syncthreads();
        for (int r = 0; r < 16; r++) {
            int p = t + 512 * r;
            int e = p & 63, tok = p >> 6;
            WORK[tok * MT_ASTR + e]      = __float_as_uint(ureg[2 * r]);
            WORK[tok * MT_ASTR + 64 + e] = __float_as_uint(ureg[2 * r + 1]);
        }
    }
    __syncthreads();
    {
        int e = t & 63, hwi = t >> 6;
        float hr = 0.f, hi = 0.f;
        for (int tt = 0; tt < 16; tt++) {
            int tok = tt * 8 + hwi;
            float ur = WORKf[tok * MT_ASTR + e];
            float ui = WORKf[tok * MT_ASTR + 64 + e];
            int ai_ = (b * 16 + tt) * 64 + e;
            float ar = g_ar[ai_], aiv = g_ai[ai_];
            float nhr = ar * hr - aiv * hi + ur;
            float nhi = ar * hi + aiv * hr + ui;
            hr = nhr; hi = nhi;
            WORK[tok * MT_ASTR + e]      = f2tf32(hr);
            WORK[tok * MT_ASTR + 64 + e] = f2tf32(hi);
        }
    }
    __syncthreads();
    {
        float4 dacc[2][2];
#pragma unroll
        for (int i = 0; i < 2; i++)
#pragma unroll
            for (int j = 0; j < 2; j++) dacc[i][j] = make_float4(0, 0, 0, 0);
        for (int kc = 0; kc < 4; kc++) {
            __syncthreads();
            {
                int kk = t >> 4, d4 = t & 15;
                *(uint4*)&B[kk * 72 + d4 * 4] =
                    *(const uint4*)&g_decB[(kc * 32 + kk) * 64 + d4 * 4];
            }
            __syncthreads();
#pragma unroll
            for (int ks = 0; ks < 4; ks++) {
                int acol = kc * 32 + ks * 8 + qc;
                uint32_t af[2][4];
#pragma unroll
                for (int mt = 0; mt < 2; mt++) {
                    int base = (wm * 32 + mt * 16) * MT_ASTR;
                    af[mt][0] = WORK[base + qr * MT_ASTR + acol];
                    af[mt][1] = WORK[base + (qr + 8) * MT_ASTR + acol];
                    af[mt][2] = WORK[base + qr * MT_ASTR + acol + 4];
                    af[mt][3] = WORK[base + (qr + 8) * MT_ASTR + acol + 4];
                }
                int br0 = (ks * 8 + qc) * 72, br1 = br0 + 4 * 72;
#pragma unroll
                for (int nt = 0; nt < 2; nt++) {
                    int j = wn * 16 + nt * 8 + qr;
                    uint32_t b0 = B[br0 + j], b1v = B[br1 + j];
                    mma_tf32(dacc[0][nt], af[0][0], af[0][1], af[0][2], af[0][3], b0, b1v);
                    mma_tf32(dacc[1][nt], af[1][0], af[1][1], af[1][2], af[1][3], b0, b1v);
                }
            }
        }
        __syncthreads();
#pragma unroll
        for (int mt = 0; mt < 2; mt++)
#pragma unroll
            for (int nt = 0; nt < 2; nt++) {
                int tok0 = wm * 32 + mt * 16 + qr;
                int d0 = wn * 16 + nt * 8 + 2 * qc;
                float4 c = dacc[mt][nt];
                DRf[d0 * 130 + tok0] = c.x;
                DRf[(d0 + 1) * 130 + tok0] = c.y;
                DRf[d0 * 130 + tok0 + 8] = c.z;
                DRf[(d0 + 1) * 130 + tok0 + 8] = c.w;
            }
    }
    __syncthreads();
    for (int r = 0; r < 32; r++) {
        int idx = t + 512 * r;
        int tok = idx >> 7, c = idx & 127;
        float v = X1[tok * MT_ASTR + c];
        if (c < 64) v += DRf[c * 130 + tok];
        X1[tok * MT_ASTR + c] = v;
        WORK[tok * MT_ASTR + c] = f2tf32(v);
    }
    __syncthreads();
    {
        int tok = t & 127, e = t >> 7;
        float l = rb[e];
        for (int c = 0; c < 128; c++)
            l = fmaf(WORKf[tok * MT_ASTR + c], rw[c * 4 + e], l);
        G[e * 128 + tok] = l;
    }
    __syncthreads();
    if (t < 128) {
        float l0 = G[t], l1 = G[128 + t], l2 = G[256 + t], l3 = G[384 + t];
        float m = fmaxf(fmaxf(l0, l1), fmaxf(l2, l3));
        float e0 = expf(l0 - m), e1 = expf(l1 - m), e2 = expf(l2 - m), e3 = expf(l3 - m);
        float inv = 1.f / (e0 + e1 + e2 + e3);
        G[t] = e0 * inv; G[128 + t] = e1 * inv;
        G[256 + t] = e2 * inv; G[384 + t] = e3 * inv;
    }
    float4 acc2[2][4];
#pragma unroll
    for (int i = 0; i < 2; i++)
#pragma unroll
        for (int j = 0; j < 4; j++) acc2[i][j] = make_float4(0, 0, 0, 0);

    for (int e = 0; e < 4; e++) {
        float4 acc1[2][4];
#pragma unroll
        for (int i = 0; i < 2; i++)
#pragma unroll
            for (int j = 0; j < 4; j++) acc1[i][j] = make_float4(0, 0, 0, 0);
        for (int kc = 0; kc < 4; kc++) {
            __syncthreads();
            for (int r = 0; r < 2; r++) {
                int idx = t + 512 * r;
                int kk = idx >> 5, j4 = idx & 31;
                *(uint4*)&B[kk * 136 + j4 * 4] =
                    *(const uint4*)&g_w1t[(size_t)e * 16384 + (kc * 32 + kk) * 128 + j4 * 4];
            }
            __syncthreads();
#pragma unroll
            for (int ks = 0; ks < 4; ks++) {
                int acol = kc * 32 + ks * 8 + qc;
                uint32_t af[2][4];
#pragma unroll
                for (int mt = 0; mt < 2; mt++) {
                    int base = (wm * 32 + mt * 16) * MT_ASTR;
                    af[mt][0] = WORK[base + qr * MT_ASTR + acol];
                    af[mt][1] = WORK[base + (qr + 8) * MT_ASTR + acol];
                    af[mt][2] = WORK[base + qr * MT_ASTR + acol + 4];
                    af[mt][3] = WORK[base + (qr + 8) * MT_ASTR + acol + 4];
                }
                int br0 = (ks * 8 + qc) * 136, br1 = br0 + 4 * 136;
#pragma unroll
                for (int nt = 0; nt < 4; nt++) {
                    int j = wn * 32 + nt * 8 + qr;
                    uint32_t b0 = B[br0 + j], b1v = B[br1 + j];
                    mma_tf32(acc1[0][nt], af[0][0], af[0][1], af[0][2], af[0][3], b0, b1v);
                    mma_tf32(acc1[1][nt], af[1][0], af[1][1], af[1][2], af[1][3], b0, b1v);
                }
            }
        }
#pragma unroll
        for (int mt = 0; mt < 2; mt++)
#pragma unroll
            for (int nt = 0; nt < 4; nt++) {
                int tok0 = wm * 32 + mt * 16 + qr;
                int j0 = wn * 32 + nt * 8 + 2 * qc;
                float4 c = acc1[mt][nt];
                float b1v0 = b1[e * 128 + j0], b1v1 = b1[e * 128 + j0 + 1];
                float g0 = G[e * 128 + tok0], g8 = G[e * 128 + tok0 + 8];
                HS[tok0 * MT_ASTR + j0]           = f2tf32(gelu_tanh(c.x + b1v0) * g0);
                HS[tok0 * MT_ASTR + j0 + 1]       = f2tf32(gelu_tanh(c.y + b1v1) * g0);
                HS[(tok0 + 8) * MT_ASTR + j0]     = f2tf32(gelu_tanh(c.z + b1v0) * g8);
                HS[(tok0 + 8) * MT_ASTR + j0 + 1] = f2tf32(gelu_tanh(c.w + b1v1) * g8);
            }
        for (int kc = 0; kc < 4; kc++) {
            __syncthreads();
            for (int r = 0; r < 2; r++) {
                int idx = t + 512 * r;
                int kk = idx >> 5, j4 = idx & 31;
                *(uint4*)&B[kk * 136 + j4 * 4] =
                    *(const uint4*)&g_w2t[(size_t)e * 16384 + (kc * 32 + kk) * 128 + j4 * 4];
            }
            __syncthreads();
#pragma unroll
            for (int ks = 0; ks < 4; ks++) {
                int acol = kc * 32 + ks * 8 + qc;
                uint32_t af[2][4];
#pragma unroll
                for (int mt = 0; mt < 2; mt++) {
                    int base = (wm * 32 + mt * 16) * MT_ASTR;
                    af[mt][0] = HS[base + qr * MT_ASTR + acol];
                    af[mt][1] = HS[base + (qr + 8) * MT_ASTR + acol];
                    af[mt][2] = HS[base + qr * MT_ASTR + acol + 4];
                    af[mt][3] = HS[base + (qr + 8) * MT_ASTR + acol + 4];
                }
                int br0 = (ks * 8 + qc) * 136, br1 = br0 + 4 * 136;
#pragma unroll
                for (int nt = 0; nt < 4; nt++) {
                    int j = wn * 32 + nt * 8 + qr;
                    uint32_t b0 = B[br0 + j], b1v = B[br1 + j];
                    mma_tf32(acc2[0][nt], af[0][0], af[0][1], af[0][2], af[0][3], b0, b1v);
                    mma_tf32(acc2[1][nt], af[1][0], af[1][1], af[1][2], af[1][3], b0, b1v);
                }
            }
        }
        __syncthreads();
    }
#pragma unroll
    for (int mt = 0; mt < 2; mt++)
#pragma unroll
        for (int nt = 0; nt < 4; nt++) {
            int tok0 = wm * 32 + mt * 16 + qr;
            int o0 = wn * 32 + nt * 8 + 2 * qc;
            float4 c = acc2[mt][nt];
            CstF[o0 * 130 + tok0] = c.x;
            CstF[(o0 + 1) * 130 + tok0] = c.y;
            CstF[o0 * 130 + tok0 + 8] = c.z;
            CstF[(o0 + 1) * 130 + tok0 + 8] = c.w;
        }
    __syncthreads();
    {
        int tl = t & 127, og = t >> 7;
        float g0 = G[tl], g1 = G[128 + tl], g2 = G[256 + tl], g3 = G[384 + tl];
        int tt = tl >> 3, hwi = tl & 7;
        int bt = b * 16 + tt;
        for (int j = 0; j < 32; j++) {
            int o = og * 32 + j;
            float delta = CstF[o * 130 + tl] +
                          g0 * b2[o] + g1 * b2[128 + o] + g2 * b2[256 + o] + g3 * b2[384 + o];
            float base = X1[tl * MT_ASTR + o];
            size_t gi = (o < 64)
                ? ((size_t)(bt * 64 + o)) * 4096 + hw0 + hwi
                : IMOFF + ((size_t)(bt * 64 + o - 64)) * 4096 + hw0 + hwi;
            out[gi] = base + delta;
        }
    }
}

extern "C" void kernel_launch(void* const* d_in, const int* in_sizes, int n_in,
                              void* d_out, int out_size) {
    const float* x_real = (const float*)d_in[0];
    const float* x_imag = (const float*)d_in[1];
    const float* dt     = (const float*)d_in[2];
    const float* nz_r   = (const float*)d_in[3];
    const float* nz_i   = (const float*)d_in[4];
    const float* ln_s_w = (const float*)d_in[5];
    const float* ln_s_b = (const float*)d_in[6];
    const float* conv_w = (const float*)d_in[7];
    const float* conv_b = (const float*)d_in[8];
    const float* ln_t_w = (const float*)d_in[9];
    const float* ln_t_b = (const float*)d_in[10];
    const float* lam_re = (const float*)d_in[11];
    const float* lam_im = (const float*)d_in[12];
    const float* sb_re  = (const float*)d_in[13];
    const float* sb_im  = (const float*)d_in[14];
    const float* enc_re = (const float*)d_in[15];
    const float* enc_im = (const float*)d_in[16];
    const float* dec_re = (const float*)d_in[17];
    const float* dec_im = (const float*)d_in[18];
    const float* rw     = (const float*)d_in[19];
    const float* rb     = (const float*)d_in[20];
    const float* w1     = (const float*)d_in[21];
    const float* b1     = (const float*)d_in[22];
    const float* w2     = (const float*)d_in[23];
    const float* b2     = (const float*)d_in[24];
    float* out = (float*)d_out;

    int conv_smem = (264 * CONV_ASTR + 3 * 32 * CONV_BSTR) * 4;  // 90240 B
    int temp_smem = (3 * 16896 + 4352 + 512 + 256) * 4;          // 223232 B
    cudaFuncSetAttribute(k_conv, cudaFuncAttributeMaxDynamicSharedMemorySize, conv_smem);
    cudaFuncSetAttribute(k_temp, cudaFuncAttributeMaxDynamicSharedMemorySize, temp_smem);

    k_wprep<<<576, 256>>>(enc_re, enc_im, dec_re, dec_im, w1, w2, conv_w);
    k_setup<<<8, 256>>>(dt, lam_re, lam_im);
    k_sln<<<2048, 256>>>(x_real, x_imag, ln_s_w, ln_s_b);
    k_conv<<<dim3(32, 32), 256, conv_smem>>>(conv_b, x_real, x_imag);
    k_temp<<<dim3(512, 2), 512, temp_smem>>>(ln_t_w, ln_t_b, sb_re, sb_im,
                                             nz_r, nz_i, rw, rb, b1, b2, out);
}